// round 10
// baseline (speedup 1.0000x reference)
#include <cuda_runtime.h>
#include <cstddef>

typedef unsigned long long ull;

#define Nn   512
#define IND  256
#define HIDD 256
#define AH   128
#define OUTD 256
#define WELD 262   // IN_DIM + 6

// ---------------- scratch ----------------
__device__ float g_F[Nn * HIDD];
__device__ float g_q[Nn * AH];
__device__ float g_qk[Nn * HIDD];
__device__ float g_w[Nn * HIDD];
__device__ float g_Gt[OUTD * HIDD];
__device__ float g_bo2[OUTD];

// ---------------- f32x2 helpers ----------------
__device__ __forceinline__ ull pack2(float lo, float hi) {
    ull r; asm("mov.b64 %0,{%1,%2};" : "=l"(r) : "f"(lo), "f"(hi)); return r;
}
__device__ __forceinline__ float2 unp2(ull x) {
    float2 f; asm("mov.b64 {%0,%1},%2;" : "=f"(f.x), "=f"(f.y) : "l"(x)); return f;
}
__device__ __forceinline__ ull fma2(ull a, ull b, ull c) {
    ull d; asm("fma.rn.f32x2 %0,%1,%2,%3;" : "=l"(d) : "l"(a), "l"(b), "l"(c)); return d;
}
__device__ __forceinline__ ull relu2(ull x) {
    ull r;
    asm("{.reg .f32 lo,hi;\n\t"
        "mov.b64 {lo,hi},%1;\n\t"
        "max.f32 lo,lo,0f00000000;\n\t"
        "max.f32 hi,hi,0f00000000;\n\t"
        "mov.b64 %0,{lo,hi};}" : "=l"(r) : "l"(x));
    return r;
}

// ================= pre kernel: F, q, Gt, bo2 in one launch ==================
// bid<128: F = app@We6^T + be         [512,256]  (TRANSB, K=256)
// bid<192: q = app@Wq^T + bq          [512,128]  (TRANSB, K=256)
// else   : Gt = Wo2@Wv                [256,256]  (non-trans, K=256)
//          + bo2 = bo + Wo2@bv (blocks with nb==0)
__global__ __launch_bounds__(256) void pre_k(
    const float* __restrict__ app,
    const float* __restrict__ We6,
    const float* __restrict__ Wq,
    const float* __restrict__ Wo2,
    const float* __restrict__ Wv,
    const float* __restrict__ be,
    const float* __restrict__ bq,
    const float* __restrict__ bv,
    const float* __restrict__ bo,
    float* __restrict__ F,
    float* __restrict__ q,
    float* __restrict__ Gt,
    float* __restrict__ bo2)
{
    __shared__ float As[2][32][34];
    __shared__ float Bs[2][32][34];
    const int t = threadIdx.x;
    const int tx = t & 15, ty = t >> 4;
    const int bid = blockIdx.x;

    const float *A, *B, *bias;
    float* C;
    int lda, ldb, ldc, mb, nb;
    bool transB, dobo2 = false;
    if (bid < 128) {
        A = app; lda = IND; B = We6; ldb = WELD; transB = true;
        bias = be; C = F; ldc = HIDD;
        mb = (bid >> 3) * 32; nb = (bid & 7) * 32;
    } else if (bid < 192) {
        int x = bid - 128;
        A = app; lda = IND; B = Wq; ldb = IND; transB = true;
        bias = bq; C = q; ldc = AH;
        mb = (x >> 2) * 32; nb = (x & 3) * 32;
    } else {
        int x = bid - 192;
        A = Wo2; lda = 2 * IND; B = Wv; ldb = HIDD; transB = false;
        bias = nullptr; C = Gt; ldc = HIDD;
        mb = (x >> 3) * 32; nb = (x & 7) * 32;
        dobo2 = (nb == 0);
    }

    float ra[4], rb[4];
#pragma unroll
    for (int r = 0; r < 4; r++) {               // prologue: tile k0 = 0
        int idx = t + r * 256, p = idx >> 5, s = idx & 31;
        ra[r] = A[(size_t)(mb + p) * lda + s];
        rb[r] = transB ? B[(size_t)(nb + p) * ldb + s]
                       : B[(size_t)p * ldb + nb + s];
    }
#pragma unroll
    for (int r = 0; r < 4; r++) {
        int idx = t + r * 256, p = idx >> 5, s = idx & 31;
        As[0][s][p] = ra[r];
        if (transB) Bs[0][s][p] = rb[r]; else Bs[0][p][s] = rb[r];
    }
    __syncthreads();

    float a00 = 0.f, a01 = 0.f, a10 = 0.f, a11 = 0.f;
    for (int step = 0; step < 8; step++) {      // K = 256
        int cur = step & 1;
        if (step < 7) {
            int k0 = (step + 1) * 32;
#pragma unroll
            for (int r = 0; r < 4; r++) {
                int idx = t + r * 256, p = idx >> 5, s = idx & 31;
                ra[r] = A[(size_t)(mb + p) * lda + k0 + s];
                rb[r] = transB ? B[(size_t)(nb + p) * ldb + k0 + s]
                               : B[(size_t)(k0 + p) * ldb + nb + s];
            }
        }
#pragma unroll
        for (int kk = 0; kk < 32; kk++) {
            float2 av = *(const float2*)&As[cur][kk][ty * 2];
            float2 bv2 = *(const float2*)&Bs[cur][kk][tx * 2];
            a00 = fmaf(av.x, bv2.x, a00);
            a01 = fmaf(av.x, bv2.y, a01);
            a10 = fmaf(av.y, bv2.x, a10);
            a11 = fmaf(av.y, bv2.y, a11);
        }
        if (step < 7) {
            __syncthreads();
            int nxt = cur ^ 1;
#pragma unroll
            for (int r = 0; r < 4; r++) {
                int idx = t + r * 256, p = idx >> 5, s = idx & 31;
                As[nxt][s][p] = ra[r];
                if (transB) Bs[nxt][s][p] = rb[r]; else Bs[nxt][p][s] = rb[r];
            }
            __syncthreads();
        }
    }

    int m = mb + ty * 2, n = nb + tx * 2;
    float b0 = bias ? bias[n] : 0.f;
    float b1 = bias ? bias[n + 1] : 0.f;
    C[(size_t)m * ldc + n]           = a00 + b0;
    C[(size_t)m * ldc + n + 1]       = a01 + b1;
    C[(size_t)(m + 1) * ldc + n]     = a10 + b0;
    C[(size_t)(m + 1) * ldc + n + 1] = a11 + b1;

    if (dobo2 && t < 32) {                       // bo2 = bo + Wo2 @ bv
        float acc = bo[mb + t];
        const float* arow = Wo2 + (size_t)(mb + t) * (2 * IND);
        for (int d = 0; d < HIDD; d++)
            acc += bv[d] * arow[d];
        bo2[mb + t] = acc;
    }
}

// ================= qk kernel: qk = (q @ Wk) * scale  [512,256], K=128 =======
__global__ __launch_bounds__(256) void qk_k(
    const float* __restrict__ q,
    const float* __restrict__ Wk,
    float* __restrict__ qk)
{
    __shared__ float As[2][32][34];
    __shared__ float Bs[2][32][34];
    const int t = threadIdx.x;
    const int tx = t & 15, ty = t >> 4;
    const int mb = (blockIdx.x >> 3) * 32, nb = (blockIdx.x & 7) * 32;

    float ra[4], rb[4];
#pragma unroll
    for (int r = 0; r < 4; r++) {
        int idx = t + r * 256, p = idx >> 5, s = idx & 31;
        ra[r] = q[(size_t)(mb + p) * AH + s];
        rb[r] = Wk[(size_t)p * HIDD + nb + s];
    }
#pragma unroll
    for (int r = 0; r < 4; r++) {
        int idx = t + r * 256, p = idx >> 5, s = idx & 31;
        As[0][s][p] = ra[r];
        Bs[0][p][s] = rb[r];
    }
    __syncthreads();

    float a00 = 0.f, a01 = 0.f, a10 = 0.f, a11 = 0.f;
    for (int step = 0; step < 4; step++) {       // K = 128
        int cur = step & 1;
        if (step < 3) {
            int k0 = (step + 1) * 32;
#pragma unroll
            for (int r = 0; r < 4; r++) {
                int idx = t + r * 256, p = idx >> 5, s = idx & 31;
                ra[r] = q[(size_t)(mb + p) * AH + k0 + s];
                rb[r] = Wk[(size_t)(k0 + p) * HIDD + nb + s];
            }
        }
#pragma unroll
        for (int kk = 0; kk < 32; kk++) {
            float2 av = *(const float2*)&As[cur][kk][ty * 2];
            float2 bv2 = *(const float2*)&Bs[cur][kk][tx * 2];
            a00 = fmaf(av.x, bv2.x, a00);
            a01 = fmaf(av.x, bv2.y, a01);
            a10 = fmaf(av.y, bv2.x, a10);
            a11 = fmaf(av.y, bv2.y, a11);
        }
        if (step < 3) {
            __syncthreads();
            int nxt = cur ^ 1;
#pragma unroll
            for (int r = 0; r < 4; r++) {
                int idx = t + r * 256, p = idx >> 5, s = idx & 31;
                As[nxt][s][p] = ra[r];
                Bs[nxt][p][s] = rb[r];
            }
            __syncthreads();
        }
    }

    const float sc = 0.08838834764831845f;
    int m = mb + ty * 2, n = nb + tx * 2;
    qk[(size_t)m * HIDD + n]           = a00 * sc;
    qk[(size_t)m * HIDD + n + 1]       = a01 * sc;
    qk[(size_t)(m + 1) * HIDD + n]     = a10 * sc;
    qk[(size_t)(m + 1) * HIDD + n + 1] = a11 * sc;
}

// ================= post kernel: out = relu([app|w] @ [Wo1;Gt]^T + bo2) ======
__global__ __launch_bounds__(256) void post_k(
    const float* __restrict__ app,
    const float* __restrict__ w,
    const float* __restrict__ Wo,
    const float* __restrict__ Gt,
    const float* __restrict__ bo2,
    float* __restrict__ out)
{
    __shared__ float As[2][32][34];
    __shared__ float Bs[2][32][34];
    const int t = threadIdx.x;
    const int tx = t & 15, ty = t >> 4;
    const int mb = (blockIdx.x >> 3) * 32, nb = (blockIdx.x & 7) * 32;

    float ra[4], rb[4];
#pragma unroll
    for (int r = 0; r < 4; r++) {
        int idx = t + r * 256, p = idx >> 5, s = idx & 31;
        ra[r] = app[(size_t)(mb + p) * IND + s];
        rb[r] = Wo[(size_t)(nb + p) * 512 + s];
    }
#pragma unroll
    for (int r = 0; r < 4; r++) {
        int idx = t + r * 256, p = idx >> 5, s = idx & 31;
        As[0][s][p] = ra[r];
        Bs[0][s][p] = rb[r];
    }
    __syncthreads();

    float a00 = 0.f, a01 = 0.f, a10 = 0.f, a11 = 0.f;
    for (int step = 0; step < 16; step++) {      // K = 512
        int cur = step & 1;
        if (step < 15) {
            int k0 = (step + 1) * 32;
#pragma unroll
            for (int r = 0; r < 4; r++) {
                int idx = t + r * 256, p = idx >> 5, s = idx & 31;
                if (k0 < 256) {
                    ra[r] = app[(size_t)(mb + p) * IND + k0 + s];
                    rb[r] = Wo[(size_t)(nb + p) * 512 + k0 + s];
                } else {
                    ra[r] = w[(size_t)(mb + p) * HIDD + (k0 - 256) + s];
                    rb[r] = Gt[(size_t)(nb + p) * HIDD + (k0 - 256) + s];
                }
            }
        }
#pragma unroll
        for (int kk = 0; kk < 32; kk++) {
            float2 av = *(const float2*)&As[cur][kk][ty * 2];
            float2 bv2 = *(const float2*)&Bs[cur][kk][tx * 2];
            a00 = fmaf(av.x, bv2.x, a00);
            a01 = fmaf(av.x, bv2.y, a01);
            a10 = fmaf(av.y, bv2.x, a10);
            a11 = fmaf(av.y, bv2.y, a11);
        }
        if (step < 15) {
            __syncthreads();
            int nxt = cur ^ 1;
#pragma unroll
            for (int r = 0; r < 4; r++) {
                int idx = t + r * 256, p = idx >> 5, s = idx & 31;
                As[nxt][s][p] = ra[r];
                Bs[nxt][s][p] = rb[r];
            }
            __syncthreads();
        }
    }

    int m = mb + ty * 2, n = nb + tx * 2;
    float b0 = bo2[n], b1 = bo2[n + 1];
    out[(size_t)m * OUTD + n]           = fmaxf(a00 + b0, 0.f);
    out[(size_t)m * OUTD + n + 1]       = fmaxf(a01 + b1, 0.f);
    out[(size_t)(m + 1) * OUTD + n]     = fmaxf(a10 + b0, 0.f);
    out[(size_t)(m + 1) * OUTD + n + 1] = fmaxf(a11 + b1, 0.f);
}

// ================= fused attention middle: 4 i-rows per block ===============
// grid 128 (1 CTA/SM, balanced). Warp w handles j = tau*8+w; lane l owns
// h = 8l..8l+7 (4 f32x2 pairs). E built once in regs; no-max softmax.
#define FU_SMEM (12288 * 8 + 256 * 17 * 8 + 32 * 4)

__global__ __launch_bounds__(256) void fused_k(
    const float* __restrict__ edges,
    const float* __restrict__ We,
    const float* __restrict__ Fm,
    const float* __restrict__ qkm,
    float* __restrict__ wout)
{
    extern __shared__ __align__(16) ull smf[];
    ull*   e2    = smf;                       // [4*512*6] dup-packed edges (96KB)
    ull*   waccs = e2 + 12288;                // [256][17] (34KB)
    float* wl    = (float*)(waccs + 256 * 17);// [8][4]

    const int t = threadIdx.x, l = t & 31, w = t >> 5;
    const int ib = blockIdx.x * 4;

    {
        const float* esrc = edges + (size_t)ib * (Nn * 6);
        for (int idx = t; idx < 4 * Nn * 6; idx += 256) {
            float v = esrc[idx];
            e2[idx] = pack2(v, v);
        }
    }

    ull W2[4][6];
#pragma unroll
    for (int k = 0; k < 4; k++) {
        int h0 = 8 * l + 2 * k;
#pragma unroll
        for (int c = 0; c < 6; c++)
            W2[k][c] = pack2(We[(size_t)h0 * WELD + c],
                             We[(size_t)(h0 + 1) * WELD + c]);
    }
    ull qk2[4][4];
#pragma unroll
    for (int i = 0; i < 4; i++) {
        const float* qa = qkm + (size_t)(ib + i) * HIDD + 8 * l;
        float4 v0 = *(const float4*)qa;
        float4 v1 = *(const float4*)(qa + 4);
        qk2[i][0] = pack2(v0.x, v0.y); qk2[i][1] = pack2(v0.z, v0.w);
        qk2[i][2] = pack2(v1.x, v1.y); qk2[i][3] = pack2(v1.z, v1.w);
    }
    __syncthreads();

    ull z = pack2(0.f, 0.f);
    ull acc[4][4];
#pragma unroll
    for (int i = 0; i < 4; i++)
#pragma unroll
        for (int k = 0; k < 4; k++) acc[i][k] = z;
    float lw[4] = {0.f, 0.f, 0.f, 0.f};

    ull Fc[4], Fn[4];
    {
        const float* fp = Fm + (size_t)w * HIDD + 8 * l;
        float4 v0 = *(const float4*)fp;
        float4 v1 = *(const float4*)(fp + 4);
        Fc[0] = pack2(v0.x, v0.y); Fc[1] = pack2(v0.z, v0.w);
        Fc[2] = pack2(v1.x, v1.y); Fc[3] = pack2(v1.z, v1.w);
    }

    for (int tau = 0; tau < 64; tau++) {
        const int jj = tau * 8 + w;
        if (tau < 63) {
            const float* fp = Fm + (size_t)(jj + 8) * HIDD + 8 * l;
            float4 v0 = *(const float4*)fp;
            float4 v1 = *(const float4*)(fp + 4);
            Fn[0] = pack2(v0.x, v0.y); Fn[1] = pack2(v0.z, v0.w);
            Fn[2] = pack2(v1.x, v1.y); Fn[3] = pack2(v1.z, v1.w);
        }
#pragma unroll
        for (int i = 0; i < 4; i++) {
            const ull* ep = e2 + (size_t)(i * Nn + jj) * 6;  // broadcast
            ull e0 = ep[0], e1 = ep[1], ee2 = ep[2];
            ull e3 = ep[3], e4 = ep[4], e5 = ep[5];
            ull g[4];
#pragma unroll
            for (int k = 0; k < 4; k++) {
                ull gg = fma2(e0, W2[k][0], Fc[k]);
                gg = fma2(e1, W2[k][1], gg);
                gg = fma2(ee2, W2[k][2], gg);
                gg = fma2(e3, W2[k][3], gg);
                gg = fma2(e4, W2[k][4], gg);
                gg = fma2(e5, W2[k][5], gg);
                g[k] = relu2(gg);
            }
            ull sd = fma2(qk2[i][0], g[0], z);
            sd = fma2(qk2[i][1], g[1], sd);
            sd = fma2(qk2[i][2], g[2], sd);
            sd = fma2(qk2[i][3], g[3], sd);
            float2 sv = unp2(sd);
            float s = sv.x + sv.y;
#pragma unroll
            for (int o = 16; o; o >>= 1)
                s += __shfl_xor_sync(0xffffffffu, s, o);
            float p = (jj == ib + i) ? 0.f : __expf(s);
            lw[i] += p;
            ull p2 = pack2(p, p);
#pragma unroll
            for (int k = 0; k < 4; k++)
                acc[i][k] = fma2(p2, g[k], acc[i][k]);
        }
#pragma unroll
        for (int k = 0; k < 4; k++) Fc[k] = Fn[k];
    }

    ull* wb = waccs + (w * 32 + l) * 17;
#pragma unroll
    for (int i = 0; i < 4; i++)
#pragma unroll
        for (int k = 0; k < 4; k++) wb[i * 4 + k] = acc[i][k];
    if (l == 0) {
#pragma unroll
        for (int i = 0; i < 4; i++) wl[w * 4 + i] = lw[i];
    }
    __syncthreads();
    for (int idx = t; idx < 512; idx += 256) {
        int i = idx >> 7, hp = idx & 127;
        int lo = hp >> 2, ko = hp & 3;
        float sx = 0.f, sy = 0.f, li = 0.f;
#pragma unroll
        for (int ww = 0; ww < 8; ww++) {
            float2 v = unp2(waccs[(ww * 32 + lo) * 17 + i * 4 + ko]);
            sx += v.x; sy += v.y;
            li += wl[ww * 4 + i];
        }
        float inv = 1.f / li;
        *(float2*)(wout + (size_t)(ib + i) * HIDD + 2 * hp) =
            make_float2(sx * inv, sy * inv);
    }
}

// ---------------- launch ----------------
extern "C" void kernel_launch(void* const* d_in, const int* in_sizes, int n_in,
                              void* d_out, int out_size)
{
    const float* app   = (const float*)d_in[0];
    const float* edges = (const float*)d_in[1];
    const float* We    = (const float*)d_in[2];
    const float* be    = (const float*)d_in[3];
    const float* Wq    = (const float*)d_in[4];
    const float* bq    = (const float*)d_in[5];
    const float* Wk    = (const float*)d_in[6];
    // d_in[7] = bk: contributes q·bk, constant per row -> cancels in softmax
    const float* Wv    = (const float*)d_in[8];
    const float* bv    = (const float*)d_in[9];
    const float* Wo    = (const float*)d_in[10];
    const float* bo    = (const float*)d_in[11];
    float* out = (float*)d_out;

    float *F, *q, *qk, *w, *Gt, *bo2;
    cudaGetSymbolAddress((void**)&F,   g_F);
    cudaGetSymbolAddress((void**)&q,   g_q);
    cudaGetSymbolAddress((void**)&qk,  g_qk);
    cudaGetSymbolAddress((void**)&w,   g_w);
    cudaGetSymbolAddress((void**)&Gt,  g_Gt);
    cudaGetSymbolAddress((void**)&bo2, g_bo2);

    cudaFuncSetAttribute(fused_k, cudaFuncAttributeMaxDynamicSharedMemorySize,
                         FU_SMEM);

    // F, q, Gt, bo2 in one launch
    pre_k<<<256, 256>>>(app, We + 6, Wq, Wo + IND, Wv, be, bq, bv, bo,
                        F, q, Gt, bo2);
    // qk = (q @ Wk) * 1/sqrt(128)
    qk_k<<<128, 256>>>(q, Wk, qk);
    // fused E-build + scores + softmax + aggregation
    fused_k<<<128, 256, FU_SMEM>>>(edges, We, F, qk, w);
    // out = relu([app|w] @ [Wo1;Gt]^T + bo2)
    post_k<<<128, 256>>>(app, w, Wo, Gt, bo2, out);
}